// round 8
// baseline (speedup 1.0000x reference)
#include <cuda_runtime.h>
#include <cuda_bf16.h>

// BackProjNet: out[65535 - v] = SCALE * sum_{j=0..1023} x[idx[v*1024+j]] * w[v*1024+j] + bias[v]
// Inputs: x (376832 f32), weight (67108864 f32), bias (65536 f32), indices (67108864 i32)
// Output: 65536 f32 (flip over both axes of 256x256 == reversed flat index).
//
// R6 ncu: L1tex 92.8% (binding), L2 82.7%, DRAM 30.4%. The random 4B gathers
// generate ~32 L1 wavefronts per warp LDG. R7: stage the first 224KB of sino
// in shared memory and route the 15.2% of gathers that hit it through the
// smem crossbar, offloading the L1tex pipe.

static constexpr int   VOXELS  = 256 * 256;     // 65536
static constexpr int   VE      = 1024;          // views * extent per voxel
static constexpr int   S_STAGE = 57344;         // floats staged in smem (224 KB)
static constexpr float SCALE_F = (float)(3.14159265358979323846 / 1024.0); // 2pi/(2*512*2)

__global__ __launch_bounds__(1024, 1)
void backproj_kernel(const float* __restrict__ sino,
                     const float* __restrict__ weight,
                     const float* __restrict__ bias,
                     const int*   __restrict__ indices,
                     float* __restrict__ out)
{
    extern __shared__ float s_sino[];

    const int tid  = threadIdx.x;
    const int lane = tid & 31;

    // Stage first S_STAGE floats of sino into smem (coalesced float4).
    {
        const float4* src = reinterpret_cast<const float4*>(sino);
        float4*       dst = reinterpret_cast<float4*>(s_sino);
        #pragma unroll
        for (int i = tid; i < S_STAGE / 4; i += 1024)
            dst[i] = src[i];
    }
    __syncthreads();

    const int warpsPerCta = 1024 / 32;                       // 32
    const int totalWarps  = gridDim.x * warpsPerCta;         // 148*32 = 4736
    const int warpGlobal  = blockIdx.x * warpsPerCta + (tid >> 5);

    // Grid-stride warp-per-voxel.
    for (int v = warpGlobal; v < VOXELS; v += totalWarps) {
        const long long base = (long long)v * VE;

        float acc = 0.0f;

        #pragma unroll
        for (int k = 0; k < 8; ++k) {
            const long long j = base + (long long)(k * 128 + lane * 4);
            const int4   i4 = __ldcs(reinterpret_cast<const int4*>(indices + j));
            const float4 w4 = __ldcs(reinterpret_cast<const float4*>(weight + j));

            const float s0 = (i4.x < S_STAGE) ? s_sino[i4.x] : __ldg(sino + i4.x);
            const float s1 = (i4.y < S_STAGE) ? s_sino[i4.y] : __ldg(sino + i4.y);
            const float s2 = (i4.z < S_STAGE) ? s_sino[i4.z] : __ldg(sino + i4.z);
            const float s3 = (i4.w < S_STAGE) ? s_sino[i4.w] : __ldg(sino + i4.w);

            acc = fmaf(s0, w4.x, acc);
            acc = fmaf(s1, w4.y, acc);
            acc = fmaf(s2, w4.z, acc);
            acc = fmaf(s3, w4.w, acc);
        }

        // Warp tree reduction.
        #pragma unroll
        for (int o = 16; o > 0; o >>= 1)
            acc += __shfl_xor_sync(0xffffffffu, acc, o);

        if (lane == 0)
            out[VOXELS - 1 - v] = acc * SCALE_F + bias[v];
    }
}

extern "C" void kernel_launch(void* const* d_in, const int* in_sizes, int n_in,
                              void* d_out, int out_size)
{
    const float* x       = (const float*)d_in[0];
    const float* weight  = (const float*)d_in[1];
    const float* bias    = (const float*)d_in[2];
    const int*   indices = (const int*)d_in[3];
    float*       out     = (float*)d_out;

    static_assert(S_STAGE % 4 == 0, "staging uses float4");
    const int smemBytes = S_STAGE * (int)sizeof(float);   // 229376 B = 224 KB

    cudaFuncSetAttribute(backproj_kernel,
                         cudaFuncAttributeMaxDynamicSharedMemorySize, smemBytes);

    // Persistent: one 1024-thread CTA per SM (224KB smem allows 1 CTA/SM).
    backproj_kernel<<<148, 1024, smemBytes>>>(x, weight, bias, indices, out);
}